// round 3
// baseline (speedup 1.0000x reference)
#include <cuda_runtime.h>

#define V0 32768
#define V1 262144
#define V2 2097152
#define OFF_CLS1 32768
#define OFF_CLS2 294912
#define OFF_OUT  2392064
#define NF4 8986624

__device__ float g_feat0[V0 * 16];
__device__ float g_h1[V1 * 16];
__device__ float g_feat1[V1 * 16];
__device__ float g_h2[V2 * 16];
__device__ unsigned char g_occ0[V0], g_gt0[V0], g_gt1[V1], g_gt2[V2];
__device__ int g_list0[V0], g_list1[V1], g_list2[V2], g_plist[V1];
__device__ unsigned long long g_keys[V2];
__device__ unsigned int g_hist[65536];

struct St {
    int mode;
    int k[3];
    int n_cand, n_parent, all, k_rem;
    unsigned long long prefix;
};
__device__ St g_st;

__device__ __forceinline__ unsigned long long make_key(float f, int idx) {
    unsigned int u = __float_as_uint(f);
    unsigned int m = (u & 0x80000000u) ? ~u : (u | 0x80000000u);
    return ((unsigned long long)m << 32) | (unsigned int)(~(unsigned int)idx);
}

__global__ void k_zero_out(float4* __restrict__ out) {
    int stride = gridDim.x * blockDim.x;
    for (int i = blockIdx.x * blockDim.x + threadIdx.x; i < NF4; i += stride)
        out[i] = make_float4(0.f, 0.f, 0.f, 0.f);
}

__global__ void k_detect(const unsigned char* __restrict__ occ0b,
                         const int* __restrict__ k0p, const int* __restrict__ k1p,
                         const int* __restrict__ k2p) {
    __shared__ int s_not01, s_off4;
    if (threadIdx.x == 0) { s_not01 = 0; s_off4 = 0; }
    __syncthreads();
    for (int i = threadIdx.x; i < 32768; i += 256) {
        unsigned char c = occ0b[i];
        if (c > 1) s_not01 = 1;
        else if (c == 1 && (i & 3)) s_off4 = 1;
    }
    __syncthreads();
    if (threadIdx.x == 0) {
        g_st.mode = s_not01 ? 2 : (s_off4 ? 0 : 1);
        int w;
        w = k0p[0]; g_st.k[0] = (w > 0 && w < (1 << 26)) ? w : 8192;
        w = k1p[0]; g_st.k[1] = (w > 0 && w < (1 << 26)) ? w : 32768;
        w = k2p[0]; g_st.k[2] = (w > 0 && w < (1 << 26)) ? w : 131072;
        g_st.n_cand = 0;
    }
}

__global__ void k_cvt(const void* __restrict__ occ0p, const void* __restrict__ gt0p,
                      const void* __restrict__ gt1p, const void* __restrict__ gt2p) {
    int mode = g_st.mode;
    int stride = gridDim.x * blockDim.x;
    for (int i = blockIdx.x * blockDim.x + threadIdx.x; i < 2 * V0 + V1 + V2; i += stride) {
        const void* src; unsigned char* dst; int li;
        if (i < V0)                 { src = occ0p; dst = g_occ0; li = i; }
        else if (i < 2 * V0)        { src = gt0p;  dst = g_gt0;  li = i - V0; }
        else if (i < 2 * V0 + V1)   { src = gt1p;  dst = g_gt1;  li = i - 2 * V0; }
        else                        { src = gt2p;  dst = g_gt2;  li = i - 2 * V0 - V1; }
        unsigned char v;
        if (mode == 0)      v = ((const unsigned char*)src)[li] != 0;
        else if (mode == 1) v = ((const int*)src)[li] != 0;
        else                v = ((const float*)src)[li] != 0.0f;
        dst[li] = v;
    }
}

__global__ void k_list0() {
    int i = blockIdx.x * blockDim.x + threadIdx.x;
    if (i >= V0 || !g_occ0[i]) return;
    int pos = atomicAdd(&g_st.n_cand, 1);
    g_list0[pos] = i;
}

// conv0: 32 -> 16, S=32, relu; weights from global (L1-cached)
__global__ void k_conv0(const float* __restrict__ x, const float* __restrict__ w,
                        const float* __restrict__ b) {
    int n = g_st.n_cand;
    int stride = gridDim.x * blockDim.x;
    for (int i = blockIdx.x * blockDim.x + threadIdx.x; i < n; i += stride) {
        int idx = g_list0[i];
        int z = idx >> 10, y = (idx >> 5) & 31, xx = idx & 31;
        float acc[16];
#pragma unroll
        for (int c = 0; c < 16; c++) acc[c] = __ldg(b + c);
#pragma unroll 1
        for (int t = 0; t < 27; t++) {
            int dz = t / 9 - 1, dy = (t / 3) % 3 - 1, dx = t % 3 - 1;
            int zz = z + dz, yy = y + dy, xc = xx + dx;
            if ((unsigned)zz >= 32u || (unsigned)yy >= 32u || (unsigned)xc >= 32u) continue;
            const float* ip = x + ((((zz << 5) + yy) << 5) + xc) * 32;
            const float* wp = w + t * 512;
#pragma unroll
            for (int ci = 0; ci < 32; ci++) {
                float a = ip[ci];
                const float4* w4 = (const float4*)(wp + ci * 16);
#pragma unroll
                for (int c4 = 0; c4 < 4; c4++) {
                    float4 ww = __ldg(w4 + c4);
                    acc[c4 * 4 + 0] += a * ww.x; acc[c4 * 4 + 1] += a * ww.y;
                    acc[c4 * 4 + 2] += a * ww.z; acc[c4 * 4 + 3] += a * ww.w;
                }
            }
        }
        float* op = g_feat0 + idx * 16;
#pragma unroll
        for (int c = 0; c < 16; c++) op[c] = fmaxf(acc[c], 0.f);
    }
}

// generic 16->16 conv3x3 over list, relu, 2 voxels/thread
__global__ void k_conv16(const float* __restrict__ in, const float* __restrict__ w,
                         const float* __restrict__ b, float* __restrict__ out,
                         const int* __restrict__ list, int S, int sb) {
    __shared__ float sw[6912];
    for (int i = threadIdx.x; i < 6912; i += blockDim.x) sw[i] = w[i];
    __syncthreads();
    int n = g_st.n_cand;
    int npair = (n + 1) >> 1;
    int stride = gridDim.x * blockDim.x;
    int M = S - 1;
    for (int i = blockIdx.x * blockDim.x + threadIdx.x; i < npair; i += stride) {
        int idx0 = list[2 * i];
        int idx1 = (2 * i + 1 < n) ? list[2 * i + 1] : idx0;
        int z0 = idx0 >> (2 * sb), y0 = (idx0 >> sb) & M, x0 = idx0 & M;
        int z1 = idx1 >> (2 * sb), y1 = (idx1 >> sb) & M, x1 = idx1 & M;
        float acc0[16], acc1[16];
#pragma unroll
        for (int c = 0; c < 16; c++) { acc0[c] = b[c]; acc1[c] = acc0[c]; }
#pragma unroll 1
        for (int t = 0; t < 27; t++) {
            int dz = t / 9 - 1, dy = (t / 3) % 3 - 1, dx = t % 3 - 1;
            int za = z0 + dz, ya = y0 + dy, xa = x0 + dx;
            int zb = z1 + dz, yb = y1 + dy, xb = x1 + dx;
            bool v0 = (unsigned)za < (unsigned)S && (unsigned)ya < (unsigned)S && (unsigned)xa < (unsigned)S;
            bool v1 = (unsigned)zb < (unsigned)S && (unsigned)yb < (unsigned)S && (unsigned)xb < (unsigned)S;
            float in0[16], in1[16];
            const float4 Z = make_float4(0.f, 0.f, 0.f, 0.f);
            const float4* p0 = (const float4*)(in + (size_t)((((za << sb) + ya) << sb) + xa) * 16);
            const float4* p1 = (const float4*)(in + (size_t)((((zb << sb) + yb) << sb) + xb) * 16);
#pragma unroll
            for (int q = 0; q < 4; q++) {
                *(float4*)(in0 + q * 4) = v0 ? p0[q] : Z;
                *(float4*)(in1 + q * 4) = v1 ? p1[q] : Z;
            }
            const float* wp = sw + t * 256;
#pragma unroll
            for (int ci = 0; ci < 16; ci++) {
                float a0 = in0[ci], a1 = in1[ci];
                const float4* w4 = (const float4*)(wp + ci * 16);
#pragma unroll
                for (int c4 = 0; c4 < 4; c4++) {
                    float4 ww = w4[c4];
                    acc0[c4 * 4 + 0] += a0 * ww.x; acc0[c4 * 4 + 1] += a0 * ww.y;
                    acc0[c4 * 4 + 2] += a0 * ww.z; acc0[c4 * 4 + 3] += a0 * ww.w;
                    acc1[c4 * 4 + 0] += a1 * ww.x; acc1[c4 * 4 + 1] += a1 * ww.y;
                    acc1[c4 * 4 + 2] += a1 * ww.z; acc1[c4 * 4 + 3] += a1 * ww.w;
                }
            }
        }
        float* o0 = out + (size_t)idx0 * 16;
#pragma unroll
        for (int c = 0; c < 16; c++) o0[c] = fmaxf(acc0[c], 0.f);
        if (2 * i + 1 < n) {
            float* o1 = out + (size_t)idx1 * 16;
#pragma unroll
            for (int c = 0; c < 16; c++) o1[c] = fmaxf(acc1[c], 0.f);
        }
    }
}

// cls conv 16->1, no relu; writes logits + keys, zeroes hist, resets select state
__global__ void k_cls16(const float* __restrict__ in, const float* __restrict__ w,
                        const float* __restrict__ b, float* __restrict__ outp,
                        const int* __restrict__ list, int S, int sb) {
    __shared__ float sw[432];
    for (int i = threadIdx.x; i < 432; i += blockDim.x) sw[i] = w[i];
    __syncthreads();
    int n = g_st.n_cand;
    int tid = blockIdx.x * blockDim.x + threadIdx.x;
    int stride = gridDim.x * blockDim.x;
    if (tid == 0) { g_st.all = 0; g_st.prefix = 0ULL; }
    int M = S - 1;
    float bias = __ldg(b);
    for (int i = tid; i < n; i += stride) {
        int idx = list[i];
        int z = idx >> (2 * sb), y = (idx >> sb) & M, x = idx & M;
        float acc = bias;
#pragma unroll 1
        for (int t = 0; t < 27; t++) {
            int dz = t / 9 - 1, dy = (t / 3) % 3 - 1, dx = t % 3 - 1;
            int zz = z + dz, yy = y + dy, xx = x + dx;
            if ((unsigned)zz >= (unsigned)S || (unsigned)yy >= (unsigned)S || (unsigned)xx >= (unsigned)S) continue;
            const float* ip = in + (size_t)((((zz << sb) + yy) << sb) + xx) * 16;
            const float* wp = sw + t * 16;
#pragma unroll
            for (int ci = 0; ci < 16; ci++) acc += ip[ci] * wp[ci];
        }
        outp[idx] = acc;
        g_keys[i] = make_key(acc, idx);
    }
    for (int i = tid; i < 65536; i += stride) g_hist[i] = 0u;
}

__global__ void k_hist(int shift, int hs) {
    if (g_st.all) return;
    int n = g_st.n_cand;
    unsigned long long pre = g_st.prefix;
    int stride = gridDim.x * blockDim.x;
    for (int i = blockIdx.x * blockDim.x + threadIdx.x; i < n; i += stride) {
        unsigned long long key = g_keys[i];
        if (hs < 64 && ((key ^ pre) >> hs)) continue;
        atomicAdd(&g_hist[(unsigned int)(key >> shift) & 0xFFFFu], 1u);
    }
}

__global__ void k_scan(int shift, int pass, int level) {
    __shared__ unsigned int csum[256];
    int t = threadIdx.x;
    unsigned int s = 0;
    for (int j = 0; j < 256; j++) s += g_hist[t * 256 + j];
    csum[t] = s;
    __syncthreads();
    if (t == 0) {
        if (pass == 0) {
            unsigned int total = 0;
            for (int c = 0; c < 256; c++) total += csum[c];
            int k = g_st.k[level];
            if ((int)total <= k) g_st.all = 1;
            g_st.k_rem = k;
        }
        if (!g_st.all) {
            int kr = g_st.k_rem;
            unsigned int cum = 0;
            int c;
            for (c = 255; c > 0; c--) {
                if (cum + csum[c] >= (unsigned)kr) break;
                cum += csum[c];
            }
            int digit = c * 256;
            for (int bq = 255; bq >= 0; bq--) {
                unsigned int h = g_hist[c * 256 + bq];
                if (cum + h >= (unsigned)kr) { digit = c * 256 + bq; break; }
                cum += h;
            }
            g_st.prefix |= ((unsigned long long)digit) << shift;
            g_st.k_rem = kr - (int)cum;
        }
        if (pass == 3) g_st.n_parent = 0;
    }
    __syncthreads();
    for (int j = 0; j < 256; j++) g_hist[t * 256 + j] = 0u;
}

__global__ void k_filter(const int* __restrict__ list, const unsigned char* __restrict__ gt,
                         float* __restrict__ outfeat, int level) {
    int n = g_st.n_cand;
    int all = g_st.all;
    unsigned long long thr = g_st.prefix;
    int stride = gridDim.x * blockDim.x;
    for (int i = blockIdx.x * blockDim.x + threadIdx.x; i < n; i += stride) {
        int idx = list[i];
        bool m = all || (g_keys[i] >= thr);
        if (gt[idx]) m = true;
        if (level < 2) {
            if (m) {
                int p = atomicAdd(&g_st.n_parent, 1);
                g_plist[p] = idx;
            }
        } else if (!m) {
            float4* p = (float4*)(outfeat + (size_t)idx * 16);
            float4 Z = make_float4(0.f, 0.f, 0.f, 0.f);
            p[0] = Z; p[1] = Z; p[2] = Z; p[3] = Z;
        }
    }
}

// conv_transpose 2x upsample (flipped kernel), relu, builds child list
__global__ void k_up(const float* __restrict__ feat, const float* __restrict__ w,
                     const float* __restrict__ b, float* __restrict__ hout,
                     int* __restrict__ listout, int S, int sb) {
    __shared__ float sw[2048];
    for (int i = threadIdx.x; i < 2048; i += blockDim.x) sw[i] = w[i];
    __syncthreads();
    int np = g_st.n_parent;
    int tid = blockIdx.x * blockDim.x + threadIdx.x;
    if (tid == 0) g_st.n_cand = np * 8;
    int total = np * 8;
    int stride = gridDim.x * blockDim.x;
    int M = S - 1;
    for (int i = tid; i < total; i += stride) {
        int p = i >> 3, j = i & 7;
        int idx = g_plist[p];
        int z = idx >> (2 * sb), y = (idx >> sb) & M, x = idx & M;
        int dz = j >> 2, dy = (j >> 1) & 1, dx = j & 1;
        int cidx = ((((2 * z + dz) << (sb + 1)) + (2 * y + dy)) << (sb + 1)) + (2 * x + dx);
        listout[i] = cidx;
        const float* wp = sw + (7 - j) * 256;  // flipped kernel
        const float* fp = feat + (size_t)idx * 16;
        float acc[16];
#pragma unroll
        for (int c = 0; c < 16; c++) acc[c] = b[c];
#pragma unroll
        for (int ci = 0; ci < 16; ci++) {
            float a = fp[ci];
            const float4* w4 = (const float4*)(wp + ci * 16);
#pragma unroll
            for (int c4 = 0; c4 < 4; c4++) {
                float4 ww = w4[c4];
                acc[c4 * 4 + 0] += a * ww.x; acc[c4 * 4 + 1] += a * ww.y;
                acc[c4 * 4 + 2] += a * ww.z; acc[c4 * 4 + 3] += a * ww.w;
            }
        }
        float* op = hout + (size_t)cidx * 16;
#pragma unroll
        for (int c = 0; c < 16; c++) op[c] = fmaxf(acc[c], 0.f);
    }
}

extern "C" void kernel_launch(void* const* d_in, const int* in_sizes, int n_in,
                              void* d_out, int out_size) {
    const float* x   = (const float*)d_in[0];
    const void* occ0 = d_in[1];
    const void* gt0  = d_in[2];
    const void* gt1  = d_in[3];
    const void* gt2  = d_in[4];
    const float* wc0 = (const float*)d_in[5],  *bc0 = (const float*)d_in[6];
    const float* wk0 = (const float*)d_in[7],  *bk0 = (const float*)d_in[8];
    const float* wu1 = (const float*)d_in[9],  *bu1 = (const float*)d_in[10];
    const float* wc1 = (const float*)d_in[11], *bc1 = (const float*)d_in[12];
    const float* wk1 = (const float*)d_in[13], *bk1 = (const float*)d_in[14];
    const float* wu2 = (const float*)d_in[15], *bu2 = (const float*)d_in[16];
    const float* wc2 = (const float*)d_in[17], *bc2 = (const float*)d_in[18];
    const float* wk2 = (const float*)d_in[19], *bk2 = (const float*)d_in[20];
    const int* n0 = (const int*)d_in[21];
    const int* n1 = (const int*)d_in[22];
    const int* n2 = (const int*)d_in[23];
    float* out = (float*)d_out;

    int* dlist0 = nullptr, *dlist1 = nullptr, *dlist2 = nullptr;
    cudaGetSymbolAddress((void**)&dlist0, g_list0);
    cudaGetSymbolAddress((void**)&dlist1, g_list1);
    cudaGetSymbolAddress((void**)&dlist2, g_list2);
    float* dh1 = nullptr, *dh2 = nullptr, *df0 = nullptr, *df1 = nullptr;
    cudaGetSymbolAddress((void**)&dh1, g_h1);
    cudaGetSymbolAddress((void**)&dh2, g_h2);
    cudaGetSymbolAddress((void**)&df0, g_feat0);
    cudaGetSymbolAddress((void**)&df1, g_feat1);
    unsigned char* dg0 = nullptr, *dg1 = nullptr, *dg2 = nullptr;
    cudaGetSymbolAddress((void**)&dg0, g_gt0);
    cudaGetSymbolAddress((void**)&dg1, g_gt1);
    cudaGetSymbolAddress((void**)&dg2, g_gt2);

    k_zero_out<<<2048, 256>>>((float4*)out);
    k_detect<<<1, 256>>>((const unsigned char*)occ0, n0, n1, n2);
    k_cvt<<<2368, 1024>>>(occ0, gt0, gt1, gt2);
    k_list0<<<128, 256>>>();
    k_conv0<<<128, 128>>>(x, wc0, bc0);

    // ---- level 0 prune ----
    k_cls16<<<592, 256>>>(df0, wk0, bk0, out, dlist0, 32, 5);
    k_hist<<<512, 256>>>(48, 64); k_scan<<<1, 256>>>(48, 0, 0);
    k_hist<<<512, 256>>>(32, 48); k_scan<<<1, 256>>>(32, 1, 0);
    k_hist<<<512, 256>>>(16, 32); k_scan<<<1, 256>>>(16, 2, 0);
    k_hist<<<512, 256>>>(0, 16);  k_scan<<<1, 256>>>(0, 3, 0);
    k_filter<<<256, 256>>>(dlist0, dg0, nullptr, 0);

    // ---- level 1 ----
    k_up<<<592, 128>>>(df0, wu1, bu1, dh1, dlist1, 32, 5);
    k_conv16<<<1184, 128>>>(dh1, wc1, bc1, df1, dlist1, 64, 6);
    k_cls16<<<592, 256>>>(df1, wk1, bk1, out + OFF_CLS1, dlist1, 64, 6);
    k_hist<<<512, 256>>>(48, 64); k_scan<<<1, 256>>>(48, 0, 1);
    k_hist<<<512, 256>>>(32, 48); k_scan<<<1, 256>>>(32, 1, 1);
    k_hist<<<512, 256>>>(16, 32); k_scan<<<1, 256>>>(16, 2, 1);
    k_hist<<<512, 256>>>(0, 16);  k_scan<<<1, 256>>>(0, 3, 1);
    k_filter<<<256, 256>>>(dlist1, dg1, nullptr, 1);

    // ---- level 2 ----
    k_up<<<1184, 128>>>(df1, wu2, bu2, dh2, dlist2, 64, 6);
    k_conv16<<<1184, 128>>>(dh2, wc2, bc2, out + OFF_OUT, dlist2, 128, 7);
    k_cls16<<<1184, 256>>>(out + OFF_OUT, wk2, bk2, out + OFF_CLS2, dlist2, 128, 7);
    k_hist<<<512, 256>>>(48, 64); k_scan<<<1, 256>>>(48, 0, 2);
    k_hist<<<512, 256>>>(32, 48); k_scan<<<1, 256>>>(32, 1, 2);
    k_hist<<<512, 256>>>(16, 32); k_scan<<<1, 256>>>(16, 2, 2);
    k_hist<<<512, 256>>>(0, 16);  k_scan<<<1, 256>>>(0, 3, 2);
    k_filter<<<512, 256>>>(dlist2, dg2, out + OFF_OUT, 2);
}